// round 14
// baseline (speedup 1.0000x reference)
#include <cuda_runtime.h>
#include <cuda_bf16.h>
#include <cstdint>
#include <math.h>

#define BB 4
#define SS 4096
#define DD 4096
#define CC 256
#define NROW (BB*SS)   // 16384 token rows

// ---------------- scratch (device globals; no allocations allowed) ----------
__device__ __nv_bfloat16 g_xn[(size_t)NROW * DD];   // normalized x, bf16
__device__ __nv_bfloat16 g_H [(size_t)NROW * CC];   // down-proj result bf16
__device__ __nv_bfloat16 g_G [(size_t)NROW * CC];   // gelu(conv(H)) bf16
__device__ __nv_bfloat16 g_wd[(size_t)CC * DD];     // w_down bf16
__device__ __nv_bfloat16 g_wu[(size_t)DD * CC];     // w_up bf16
__device__ float         g_wc[3][CC];               // transposed conv weights
__device__ float         g_gate[NROW];              // per-token sigmoid gate

// ---------------- helpers -----------------------------------------------------
__device__ __forceinline__ void cp16(void* dst_smem, const void* src_gmem) {
    uint32_t d = (uint32_t)__cvta_generic_to_shared(dst_smem);
    asm volatile("cp.async.cg.shared.global [%0], [%1], 16;\n" :: "r"(d), "l"(src_gmem));
}
__device__ __forceinline__ void cp_commit() { asm volatile("cp.async.commit_group;\n"); }

__device__ __forceinline__ float gelu_exact(float v) {
    return 0.5f * v * (1.0f + erff(v * 0.70710678118654752f));
}

// ---------------- kernel 1: fused weight-convert + LN/gate -------------------
__global__ __launch_bounds__(256) void k_lncvt(const float4* __restrict__ x,
                                               const float* __restrict__ gamma,
                                               const float* __restrict__ beta,
                                               const float4* __restrict__ wg,
                                               const float* __restrict__ b_gate,
                                               const float* __restrict__ wd,
                                               const float* __restrict__ wu,
                                               const float* __restrict__ wc) {
    if (blockIdx.x >= NROW) {
        int i = (blockIdx.x - NROW) * 256 + threadIdx.x;   // 0 .. CC*DD-1
        g_wd[i] = __float2bfloat16(wd[i]);
        g_wu[i] = __float2bfloat16(wu[i]);
        if (i < CC * 3) g_wc[i % 3][i / 3] = wc[i];
        return;
    }

    int row = blockIdx.x;
    int t = threadIdx.x;
    const float4* xr = x + (size_t)row * (DD / 4);

    float4 v[4];
    float s = 0.f, ss = 0.f, gd = 0.f;
#pragma unroll
    for (int i = 0; i < 4; i++) {
        int idx = t + i * 256;
        float4 a = xr[idx];
        v[i] = a;
        float4 w = wg[idx];
        s  += a.x + a.y + a.z + a.w;
        ss += a.x * a.x + a.y * a.y + a.z * a.z + a.w * a.w;
        gd += a.x * w.x + a.y * w.y + a.z * w.z + a.w * w.w;
    }

    __shared__ float red[3][8];
    int lane = t & 31, warp = t >> 5;
#pragma unroll
    for (int off = 16; off; off >>= 1) {
        s  += __shfl_down_sync(0xffffffffu, s,  off);
        ss += __shfl_down_sync(0xffffffffu, ss, off);
        gd += __shfl_down_sync(0xffffffffu, gd, off);
    }
    if (lane == 0) { red[0][warp] = s; red[1][warp] = ss; red[2][warp] = gd; }
    __syncthreads();
    if (warp == 0) {
        s  = (lane < 8) ? red[0][lane] : 0.f;
        ss = (lane < 8) ? red[1][lane] : 0.f;
        gd = (lane < 8) ? red[2][lane] : 0.f;
#pragma unroll
        for (int off = 4; off; off >>= 1) {
            s  += __shfl_down_sync(0xffffffffu, s,  off);
            ss += __shfl_down_sync(0xffffffffu, ss, off);
            gd += __shfl_down_sync(0xffffffffu, gd, off);
        }
        if (lane == 0) { red[0][0] = s; red[1][0] = ss; red[2][0] = gd; }
    }
    __syncthreads();
    s = red[0][0]; ss = red[1][0]; gd = red[2][0];

    const float inv_d = 1.0f / (float)DD;
    float mu = s * inv_d;
    float var = ss * inv_d - mu * mu;
    float rstd = rsqrtf(var + 1e-5f);

    if (t == 0) {
        float z = gd + b_gate[0];
        g_gate[row] = 1.0f / (1.0f + expf(-z));
    }

    __nv_bfloat162* outr = ((__nv_bfloat162*)g_xn) + (size_t)row * (DD / 2);
    const float4* g4p = (const float4*)gamma;
    const float4* b4p = (const float4*)beta;
#pragma unroll
    for (int i = 0; i < 4; i++) {
        int idx = t + i * 256;
        float4 a = v[i];
        float4 g4 = g4p[idx];
        float4 b4 = b4p[idx];
        float nx = (a.x - mu) * rstd * g4.x + b4.x;
        float ny = (a.y - mu) * rstd * g4.y + b4.y;
        float nz = (a.z - mu) * rstd * g4.z + b4.z;
        float nw = (a.w - mu) * rstd * g4.w + b4.w;
        outr[idx * 2 + 0] = __floats2bfloat162_rn(nx, ny);
        outr[idx * 2 + 1] = __floats2bfloat162_rn(nz, nw);
    }
}

// ---------------- GEMM: C[M,N] = A[M,K] * B[N,K]^T, BK=32, 3-stage -----------
// R4 proven schedule: prefetch kt+2 issued BEFORE waiting on kt.
// Anti-phase kk: wm=0 warps do kk 0->16, wm=1 warps do 16->0, so half the
// warps LDSM while the other half MMA (breaks barrier phase lockstep).
// B fragments loaded with ldmatrix.x4 (2 n-tiles per instruction).
// EPI==0: write bf16 to g_H. A = g_xn, B = g_wd.
// EPI==1: out = x + gate * acc. A = g_G, B = g_wu.
#define STG 20480                       // bytes per stage: A 128x80 + B 128x80
#define GEMM_SMEM (3 * STG)

template <int N_TOTAL, int K_TOTAL, int EPI>
__global__ __launch_bounds__(256, 2) void gemm_bf16(const float* __restrict__ x,
                                                    float* __restrict__ out) {
    extern __shared__ char dsm[];

    const __nv_bfloat16* A = (EPI == 0) ? g_xn : g_G;
    const __nv_bfloat16* B = (EPI == 0) ? g_wd : g_wu;

    int t = threadIdx.x;
    int lane = t & 31, warp = t >> 5;
    int wm = warp >> 2;      // 0..1
    int wn = warp & 3;       // 0..3

    const __nv_bfloat16* Ablk = A + (size_t)blockIdx.y * 128 * K_TOTAL;
    const __nv_bfloat16* Bblk = B + (size_t)blockIdx.x * 128 * K_TOTAL;

    float acc[4][4][4];
#pragma unroll
    for (int i = 0; i < 4; i++)
#pragma unroll
        for (int j = 0; j < 4; j++)
#pragma unroll
            for (int k = 0; k < 4; k++) acc[i][j][k] = 0.f;

    auto load_stage = [&](int st, int kt) {
        int k0 = kt * 32;
        char* sa = dsm + st * STG;
        char* sb = sa + 10240;
#pragma unroll
        for (int j = 0; j < 2; j++) {
            int ch = t + j * 256;          // 0..511
            int row = ch >> 2;
            int kc = ch & 3;
            cp16(sa + row * 80 + kc * 16, Ablk + (size_t)row * K_TOTAL + k0 + kc * 8);
            cp16(sb + row * 80 + kc * 16, Bblk + (size_t)row * K_TOTAL + k0 + kc * 8);
        }
        cp_commit();
    };

    const int nk = K_TOTAL / 32;
    load_stage(0, 0);
    load_stage(1, 1);

    const int kk0 = wm << 4;            // anti-phase start: wm=0 -> 0, wm=1 -> 16

    for (int kt = 0; kt < nk; ++kt) {
        // issue prefetch for kt+2 BEFORE waiting on kt: ~2-iteration distance
        if (kt + 2 < nk) {
            load_stage((kt + 2) % 3, kt + 2);
            asm volatile("cp.async.wait_group 2;\n" ::: "memory");
        } else if (kt + 1 < nk) {
            asm volatile("cp.async.wait_group 1;\n" ::: "memory");
        } else {
            asm volatile("cp.async.wait_group 0;\n" ::: "memory");
        }
        __syncthreads();

        char* sa = dsm + (kt % 3) * STG;
        char* sb = sa + 10240;
#pragma unroll
        for (int s = 0; s < 2; s++) {
            int kk = kk0 ^ (s << 4);    // wm=0: 0,16  wm=1: 16,0
            uint32_t a[4][4];
#pragma unroll
            for (int im = 0; im < 4; im++) {
                uint32_t addr = (uint32_t)__cvta_generic_to_shared(
                    sa + (wm * 64 + im * 16 + (lane & 15)) * 80 + (kk + ((lane >> 4) << 3)) * 2);
                asm volatile("ldmatrix.sync.aligned.m8n8.x4.shared.b16 {%0,%1,%2,%3}, [%4];\n"
                             : "=r"(a[im][0]), "=r"(a[im][1]), "=r"(a[im][2]), "=r"(a[im][3])
                             : "r"(addr));
            }
            uint32_t b[4][2];
#pragma unroll
            for (int in2 = 0; in2 < 2; in2++) {
                // x4: mats 0/1 = n rows in2*16..+7 (k halves 0,1); mats 2/3 = +8 rows
                int row = wn * 32 + in2 * 16 + ((lane >> 4) << 3) + (lane & 7);
                int col = kk + (((lane >> 3) & 1) << 3);
                uint32_t addr = (uint32_t)__cvta_generic_to_shared(
                    sb + row * 80 + col * 2);
                asm volatile("ldmatrix.sync.aligned.m8n8.x4.shared.b16 {%0,%1,%2,%3}, [%4];\n"
                             : "=r"(b[2*in2][0]), "=r"(b[2*in2][1]),
                               "=r"(b[2*in2+1][0]), "=r"(b[2*in2+1][1])
                             : "r"(addr));
            }
#pragma unroll
            for (int im = 0; im < 4; im++)
#pragma unroll
                for (int in_ = 0; in_ < 4; in_++)
                    asm volatile(
                        "mma.sync.aligned.m16n8k16.row.col.f32.bf16.bf16.f32 "
                        "{%0,%1,%2,%3}, {%4,%5,%6,%7}, {%8,%9}, {%0,%1,%2,%3};\n"
                        : "+f"(acc[im][in_][0]), "+f"(acc[im][in_][1]),
                          "+f"(acc[im][in_][2]), "+f"(acc[im][in_][3])
                        : "r"(a[im][0]), "r"(a[im][1]), "r"(a[im][2]), "r"(a[im][3]),
                          "r"(b[in_][0]), "r"(b[in_][1]));
        }
        __syncthreads();
    }

    // epilogue
    int r = lane >> 2;
    int cp2 = (lane & 3) * 2;
    int m_base = blockIdx.y * 128 + wm * 64;
    int n_base = blockIdx.x * 128 + wn * 32;

    if (EPI == 0) {
#pragma unroll
        for (int im = 0; im < 4; im++) {
            int m = m_base + im * 16 + r;
#pragma unroll
            for (int in_ = 0; in_ < 4; in_++) {
                int n = n_base + in_ * 8 + cp2;
                __nv_bfloat162 p0 = __floats2bfloat162_rn(acc[im][in_][0], acc[im][in_][1]);
                __nv_bfloat162 p1 = __floats2bfloat162_rn(acc[im][in_][2], acc[im][in_][3]);
                *(__nv_bfloat162*)&g_H[(size_t)m * N_TOTAL + n] = p0;
                *(__nv_bfloat162*)&g_H[(size_t)(m + 8) * N_TOTAL + n] = p1;
            }
        }
    } else {
#pragma unroll
        for (int im = 0; im < 4; im++) {
            int m = m_base + im * 16 + r;
            float gA = g_gate[m];
            float gB = g_gate[m + 8];
#pragma unroll
            for (int in_ = 0; in_ < 4; in_++) {
                int n = n_base + in_ * 8 + cp2;
                float2 xv0 = *(const float2*)&x[(size_t)m * DD + n];
                float2 xv1 = *(const float2*)&x[(size_t)(m + 8) * DD + n];
                float2 o0 = make_float2(xv0.x + gA * acc[im][in_][0],
                                        xv0.y + gA * acc[im][in_][1]);
                float2 o1 = make_float2(xv1.x + gB * acc[im][in_][2],
                                        xv1.y + gB * acc[im][in_][3]);
                *(float2*)&out[(size_t)m * DD + n] = o0;
                *(float2*)&out[(size_t)(m + 8) * DD + n] = o1;
            }
        }
    }
}

// ---------------- kernel 3: depthwise conv(k=3) + exact GELU -> bf16 ---------
__global__ __launch_bounds__(256) void k_conv() {
    int t = threadIdx.x;
    int row = blockIdx.x * 4 + (t >> 6);
    int c4 = t & 63;
    int s = row & (SS - 1);

    const uint2* Hc = ((const uint2*)g_H) + (size_t)row * (CC / 4);
    uint2 zz = make_uint2(0u, 0u);
    uint2 um = (s > 0)      ? Hc[c4 - (CC / 4)] : zz;
    uint2 uc = Hc[c4];
    uint2 up = (s < SS - 1) ? Hc[c4 + (CC / 4)] : zz;

    float2 m0 = __bfloat1622float2(*(__nv_bfloat162*)&um.x);
    float2 m1 = __bfloat1622float2(*(__nv_bfloat162*)&um.y);
    float2 c0 = __bfloat1622float2(*(__nv_bfloat162*)&uc.x);
    float2 c1 = __bfloat1622float2(*(__nv_bfloat162*)&uc.y);
    float2 p0 = __bfloat1622float2(*(__nv_bfloat162*)&up.x);
    float2 p1 = __bfloat1622float2(*(__nv_bfloat162*)&up.y);

    float4 w0 = ((const float4*)g_wc[0])[c4];
    float4 w1 = ((const float4*)g_wc[1])[c4];
    float4 w2 = ((const float4*)g_wc[2])[c4];

    float vx = gelu_exact(m0.x * w0.x + c0.x * w1.x + p0.x * w2.x);
    float vy = gelu_exact(m0.y * w0.y + c0.y * w1.y + p0.y * w2.y);
    float vz = gelu_exact(m1.x * w0.z + c1.x * w1.z + p1.x * w2.z);
    float vw = gelu_exact(m1.y * w0.w + c1.y * w1.w + p1.y * w2.w);

    __nv_bfloat162* G2 = ((__nv_bfloat162*)g_G) + (size_t)row * (CC / 2);
    G2[c4 * 2 + 0] = __floats2bfloat162_rn(vx, vy);
    G2[c4 * 2 + 1] = __floats2bfloat162_rn(vz, vw);
}

// ---------------- launch ------------------------------------------------------
extern "C" void kernel_launch(void* const* d_in, const int* in_sizes, int n_in,
                              void* d_out, int out_size) {
    const float* x      = (const float*)d_in[0];
    const float* gamma  = (const float*)d_in[1];
    const float* beta   = (const float*)d_in[2];
    const float* w_down = (const float*)d_in[3];
    const float* w_conv = (const float*)d_in[4];
    const float* w_up   = (const float*)d_in[5];
    const float* w_gate = (const float*)d_in[6];
    const float* b_gate = (const float*)d_in[7];
    float* out = (float*)d_out;

    cudaFuncSetAttribute(gemm_bf16<CC, DD, 0>,
                         cudaFuncAttributeMaxDynamicSharedMemorySize, GEMM_SMEM);
    cudaFuncSetAttribute(gemm_bf16<DD, CC, 1>,
                         cudaFuncAttributeMaxDynamicSharedMemorySize, GEMM_SMEM);

    // 4 launches; ncu capture slot (4th launch) lands on gemm2
    k_lncvt<<<NROW + 4096, 256>>>((const float4*)x, gamma, beta, (const float4*)w_gate,
                                  b_gate, w_down, w_up, w_conv);
    gemm_bf16<CC, DD, 0><<<dim3(CC / 128, NROW / 128), 256, GEMM_SMEM>>>(nullptr, nullptr);
    k_conv<<<NROW / 4, 256>>>();
    gemm_bf16<DD, CC, 1><<<dim3(DD / 128, NROW / 128), 256, GEMM_SMEM>>>(x, out);
}

// round 15
// speedup vs baseline: 1.0247x; 1.0247x over previous
#include <cuda_runtime.h>
#include <cuda_bf16.h>
#include <cstdint>
#include <math.h>

#define BB 4
#define SS 4096
#define DD 4096
#define CC 256
#define NROW (BB*SS)   // 16384 token rows

// ---------------- scratch (device globals; no allocations allowed) ----------
__device__ __nv_bfloat16 g_xn[(size_t)NROW * DD];   // normalized x, bf16
__device__ __nv_bfloat16 g_H [(size_t)NROW * CC];   // down-proj result bf16
__device__ __nv_bfloat16 g_G [(size_t)NROW * CC];   // gelu(conv(H)) bf16
__device__ __nv_bfloat16 g_wd[(size_t)CC * DD];     // w_down bf16
__device__ __nv_bfloat16 g_wu[(size_t)DD * CC];     // w_up bf16
__device__ float         g_wc[3][CC];               // transposed conv weights
__device__ float         g_gate[NROW];              // per-token sigmoid gate

// ---------------- helpers -----------------------------------------------------
__device__ __forceinline__ void cp16(void* dst_smem, const void* src_gmem) {
    uint32_t d = (uint32_t)__cvta_generic_to_shared(dst_smem);
    asm volatile("cp.async.cg.shared.global [%0], [%1], 16;\n" :: "r"(d), "l"(src_gmem));
}
__device__ __forceinline__ void cp_commit() { asm volatile("cp.async.commit_group;\n"); }

__device__ __forceinline__ float gelu_exact(float v) {
    return 0.5f * v * (1.0f + erff(v * 0.70710678118654752f));
}

// ---------------- kernel 1: fused weight-convert + LN/gate -------------------
// Blocks [0, NROW): LayerNorm + gate for one token row.
// Blocks [NROW, NROW+4096): convert w_down/w_up/w_conv (1 elem per thread).
__global__ __launch_bounds__(256) void k_lncvt(const float4* __restrict__ x,
                                               const float* __restrict__ gamma,
                                               const float* __restrict__ beta,
                                               const float4* __restrict__ wg,
                                               const float* __restrict__ b_gate,
                                               const float* __restrict__ wd,
                                               const float* __restrict__ wu,
                                               const float* __restrict__ wc) {
    if (blockIdx.x >= NROW) {
        int i = (blockIdx.x - NROW) * 256 + threadIdx.x;   // 0 .. CC*DD-1
        g_wd[i] = __float2bfloat16(wd[i]);
        g_wu[i] = __float2bfloat16(wu[i]);
        if (i < CC * 3) g_wc[i % 3][i / 3] = wc[i];
        return;
    }

    int row = blockIdx.x;
    int t = threadIdx.x;
    const float4* xr = x + (size_t)row * (DD / 4);

    float4 v[4];
    float s = 0.f, ss = 0.f, gd = 0.f;
#pragma unroll
    for (int i = 0; i < 4; i++) {
        int idx = t + i * 256;
        float4 a = xr[idx];
        v[i] = a;
        float4 w = wg[idx];
        s  += a.x + a.y + a.z + a.w;
        ss += a.x * a.x + a.y * a.y + a.z * a.z + a.w * a.w;
        gd += a.x * w.x + a.y * w.y + a.z * w.z + a.w * w.w;
    }

    __shared__ float red[3][8];
    int lane = t & 31, warp = t >> 5;
#pragma unroll
    for (int off = 16; off; off >>= 1) {
        s  += __shfl_down_sync(0xffffffffu, s,  off);
        ss += __shfl_down_sync(0xffffffffu, ss, off);
        gd += __shfl_down_sync(0xffffffffu, gd, off);
    }
    if (lane == 0) { red[0][warp] = s; red[1][warp] = ss; red[2][warp] = gd; }
    __syncthreads();
    if (warp == 0) {
        s  = (lane < 8) ? red[0][lane] : 0.f;
        ss = (lane < 8) ? red[1][lane] : 0.f;
        gd = (lane < 8) ? red[2][lane] : 0.f;
#pragma unroll
        for (int off = 4; off; off >>= 1) {
            s  += __shfl_down_sync(0xffffffffu, s,  off);
            ss += __shfl_down_sync(0xffffffffu, ss, off);
            gd += __shfl_down_sync(0xffffffffu, gd, off);
        }
        if (lane == 0) { red[0][0] = s; red[1][0] = ss; red[2][0] = gd; }
    }
    __syncthreads();
    s = red[0][0]; ss = red[1][0]; gd = red[2][0];

    const float inv_d = 1.0f / (float)DD;
    float mu = s * inv_d;
    float var = ss * inv_d - mu * mu;
    float rstd = rsqrtf(var + 1e-5f);

    if (t == 0) {
        float z = gd + b_gate[0];
        g_gate[row] = 1.0f / (1.0f + expf(-z));
    }

    __nv_bfloat162* outr = ((__nv_bfloat162*)g_xn) + (size_t)row * (DD / 2);
    const float4* g4p = (const float4*)gamma;
    const float4* b4p = (const float4*)beta;
#pragma unroll
    for (int i = 0; i < 4; i++) {
        int idx = t + i * 256;
        float4 a = v[i];
        float4 g4 = g4p[idx];
        float4 b4 = b4p[idx];
        float nx = (a.x - mu) * rstd * g4.x + b4.x;
        float ny = (a.y - mu) * rstd * g4.y + b4.y;
        float nz = (a.z - mu) * rstd * g4.z + b4.z;
        float nw = (a.w - mu) * rstd * g4.w + b4.w;
        outr[idx * 2 + 0] = __floats2bfloat162_rn(nx, ny);
        outr[idx * 2 + 1] = __floats2bfloat162_rn(nz, nw);
    }
}

// ---------------- GEMM: C[M,N] = A[M,K] * B[N,K]^T, BK=32, 3-stage -----------
// R4 proven schedule (unchanged): prefetch kt+2 issued BEFORE waiting on kt.
// BM=128, BN=128, 256 threads (8 warps = 2x4), warp tile 64x32.
// EPI==0: write bf16 to g_H. A = g_xn, B = g_wd.
// EPI==1: out = x + gate * acc. A = g_G, B = g_wu.
#define STG 20480                       // bytes per stage: A 128x80 + B 128x80
#define GEMM_SMEM (3 * STG)

template <int N_TOTAL, int K_TOTAL, int EPI>
__global__ __launch_bounds__(256, 2) void gemm_bf16(const float* __restrict__ x,
                                                    float* __restrict__ out) {
    extern __shared__ char dsm[];

    const __nv_bfloat16* A = (EPI == 0) ? g_xn : g_G;
    const __nv_bfloat16* B = (EPI == 0) ? g_wd : g_wu;

    int t = threadIdx.x;
    int lane = t & 31, warp = t >> 5;
    int wm = warp >> 2;      // 0..1
    int wn = warp & 3;       // 0..3

    const __nv_bfloat16* Ablk = A + (size_t)blockIdx.y * 128 * K_TOTAL;
    const __nv_bfloat16* Bblk = B + (size_t)blockIdx.x * 128 * K_TOTAL;

    float acc[4][4][4];
#pragma unroll
    for (int i = 0; i < 4; i++)
#pragma unroll
        for (int j = 0; j < 4; j++)
#pragma unroll
            for (int k = 0; k < 4; k++) acc[i][j][k] = 0.f;

    auto load_stage = [&](int st, int kt) {
        int k0 = kt * 32;
        char* sa = dsm + st * STG;
        char* sb = sa + 10240;
#pragma unroll
        for (int j = 0; j < 2; j++) {
            int ch = t + j * 256;          // 0..511
            int row = ch >> 2;
            int kc = ch & 3;
            cp16(sa + row * 80 + kc * 16, Ablk + (size_t)row * K_TOTAL + k0 + kc * 8);
            cp16(sb + row * 80 + kc * 16, Bblk + (size_t)row * K_TOTAL + k0 + kc * 8);
        }
        cp_commit();
    };

    const int nk = K_TOTAL / 32;
    load_stage(0, 0);
    load_stage(1, 1);

    for (int kt = 0; kt < nk; ++kt) {
        // issue prefetch for kt+2 BEFORE waiting on kt: ~2-iteration distance
        if (kt + 2 < nk) {
            load_stage((kt + 2) % 3, kt + 2);
            asm volatile("cp.async.wait_group 2;\n" ::: "memory");
        } else if (kt + 1 < nk) {
            asm volatile("cp.async.wait_group 1;\n" ::: "memory");
        } else {
            asm volatile("cp.async.wait_group 0;\n" ::: "memory");
        }
        __syncthreads();

        char* sa = dsm + (kt % 3) * STG;
        char* sb = sa + 10240;
#pragma unroll
        for (int kk = 0; kk < 32; kk += 16) {
            uint32_t a[4][4];
#pragma unroll
            for (int im = 0; im < 4; im++) {
                uint32_t addr = (uint32_t)__cvta_generic_to_shared(
                    sa + (wm * 64 + im * 16 + (lane & 15)) * 80 + (kk + ((lane >> 4) << 3)) * 2);
                asm volatile("ldmatrix.sync.aligned.m8n8.x4.shared.b16 {%0,%1,%2,%3}, [%4];\n"
                             : "=r"(a[im][0]), "=r"(a[im][1]), "=r"(a[im][2]), "=r"(a[im][3])
                             : "r"(addr));
            }
            uint32_t b[4][2];
#pragma unroll
            for (int in_ = 0; in_ < 4; in_++) {
                uint32_t addr = (uint32_t)__cvta_generic_to_shared(
                    sb + (wn * 32 + in_ * 8 + (lane & 7)) * 80 + (kk + (((lane >> 3) & 1) << 3)) * 2);
                asm volatile("ldmatrix.sync.aligned.m8n8.x2.shared.b16 {%0,%1}, [%2];\n"
                             : "=r"(b[in_][0]), "=r"(b[in_][1])
                             : "r"(addr));
            }
#pragma unroll
            for (int im = 0; im < 4; im++)
#pragma unroll
                for (int in_ = 0; in_ < 4; in_++)
                    asm volatile(
                        "mma.sync.aligned.m16n8k16.row.col.f32.bf16.bf16.f32 "
                        "{%0,%1,%2,%3}, {%4,%5,%6,%7}, {%8,%9}, {%0,%1,%2,%3};\n"
                        : "+f"(acc[im][in_][0]), "+f"(acc[im][in_][1]),
                          "+f"(acc[im][in_][2]), "+f"(acc[im][in_][3])
                        : "r"(a[im][0]), "r"(a[im][1]), "r"(a[im][2]), "r"(a[im][3]),
                          "r"(b[in_][0]), "r"(b[in_][1]));
        }
        __syncthreads();
    }

    // epilogue
    int r = lane >> 2;
    int cp2 = (lane & 3) * 2;
    int m_base = blockIdx.y * 128 + wm * 64;
    int n_base = blockIdx.x * 128 + wn * 32;

    if (EPI == 0) {
#pragma unroll
        for (int im = 0; im < 4; im++) {
            int m = m_base + im * 16 + r;
#pragma unroll
            for (int in_ = 0; in_ < 4; in_++) {
                int n = n_base + in_ * 8 + cp2;
                __nv_bfloat162 p0 = __floats2bfloat162_rn(acc[im][in_][0], acc[im][in_][1]);
                __nv_bfloat162 p1 = __floats2bfloat162_rn(acc[im][in_][2], acc[im][in_][3]);
                *(__nv_bfloat162*)&g_H[(size_t)m * N_TOTAL + n] = p0;
                *(__nv_bfloat162*)&g_H[(size_t)(m + 8) * N_TOTAL + n] = p1;
            }
        }
    } else {
#pragma unroll
        for (int im = 0; im < 4; im++) {
            int m = m_base + im * 16 + r;
            float gA = g_gate[m];
            float gB = g_gate[m + 8];
#pragma unroll
            for (int in_ = 0; in_ < 4; in_++) {
                int n = n_base + in_ * 8 + cp2;
                float2 xv0 = *(const float2*)&x[(size_t)m * DD + n];
                float2 xv1 = *(const float2*)&x[(size_t)(m + 8) * DD + n];
                float2 o0 = make_float2(xv0.x + gA * acc[im][in_][0],
                                        xv0.y + gA * acc[im][in_][1]);
                float2 o1 = make_float2(xv1.x + gB * acc[im][in_][2],
                                        xv1.y + gB * acc[im][in_][3]);
                *(float2*)&out[(size_t)m * DD + n] = o0;
                *(float2*)&out[(size_t)(m + 8) * DD + n] = o1;
            }
        }
    }
}

// ---------------- kernel 3: depthwise conv(k=3) + exact GELU -> bf16 ---------
__global__ __launch_bounds__(256) void k_conv() {
    int t = threadIdx.x;
    int row = blockIdx.x * 4 + (t >> 6);
    int c4 = t & 63;                       // 4-channel group
    int s = row & (SS - 1);

    const uint2* Hc = ((const uint2*)g_H) + (size_t)row * (CC / 4);   // 4 bf16 = 8B
    uint2 zz = make_uint2(0u, 0u);
    uint2 um = (s > 0)      ? Hc[c4 - (CC / 4)] : zz;
    uint2 uc = Hc[c4];
    uint2 up = (s < SS - 1) ? Hc[c4 + (CC / 4)] : zz;

    float2 m0 = __bfloat1622float2(*(__nv_bfloat162*)&um.x);
    float2 m1 = __bfloat1622float2(*(__nv_bfloat162*)&um.y);
    float2 c0 = __bfloat1622float2(*(__nv_bfloat162*)&uc.x);
    float2 c1 = __bfloat1622float2(*(__nv_bfloat162*)&uc.y);
    float2 p0 = __bfloat1622float2(*(__nv_bfloat162*)&up.x);
    float2 p1 = __bfloat1622float2(*(__nv_bfloat162*)&up.y);

    float4 w0 = ((const float4*)g_wc[0])[c4];
    float4 w1 = ((const float4*)g_wc[1])[c4];
    float4 w2 = ((const float4*)g_wc[2])[c4];

    float vx = gelu_exact(m0.x * w0.x + c0.x * w1.x + p0.x * w2.x);
    float vy = gelu_exact(m0.y * w0.y + c0.y * w1.y + p0.y * w2.y);
    float vz = gelu_exact(m1.x * w0.z + c1.x * w1.z + p1.x * w2.z);
    float vw = gelu_exact(m1.y * w0.w + c1.y * w1.w + p1.y * w2.w);

    __nv_bfloat162* G2 = ((__nv_bfloat162*)g_G) + (size_t)row * (CC / 2);
    G2[c4 * 2 + 0] = __floats2bfloat162_rn(vx, vy);
    G2[c4 * 2 + 1] = __floats2bfloat162_rn(vz, vw);
}

// ---------------- launch ------------------------------------------------------
extern "C" void kernel_launch(void* const* d_in, const int* in_sizes, int n_in,
                              void* d_out, int out_size) {
    const float* x      = (const float*)d_in[0];
    const float* gamma  = (const float*)d_in[1];
    const float* beta   = (const float*)d_in[2];
    const float* w_down = (const float*)d_in[3];
    const float* w_conv = (const float*)d_in[4];
    const float* w_up   = (const float*)d_in[5];
    const float* w_gate = (const float*)d_in[6];
    const float* b_gate = (const float*)d_in[7];
    float* out = (float*)d_out;

    cudaFuncSetAttribute(gemm_bf16<CC, DD, 0>,
                         cudaFuncAttributeMaxDynamicSharedMemorySize, GEMM_SMEM);
    cudaFuncSetAttribute(gemm_bf16<DD, CC, 1>,
                         cudaFuncAttributeMaxDynamicSharedMemorySize, GEMM_SMEM);

    // 4 launches; ncu capture slot (4th launch) lands on gemm2
    k_lncvt<<<NROW + 4096, 256>>>((const float4*)x, gamma, beta, (const float4*)w_gate,
                                  b_gate, w_down, w_up, w_conv);
    gemm_bf16<CC, DD, 0><<<dim3(CC / 128, NROW / 128), 256, GEMM_SMEM>>>(nullptr, nullptr);
    k_conv<<<NROW / 4, 256>>>();
    gemm_bf16<DD, CC, 1><<<dim3(DD / 128, NROW / 128), 256, GEMM_SMEM>>>(x, out);
}